// round 2
// baseline (speedup 1.0000x reference)
#include <cuda_runtime.h>

// Net_2095944040841: 3-layer LSTM (reference's buggy c-state wiring) on GB300.
// R2: 4-way FMA chains, warp 7 specialization (x prefetch + out-proj overlap).

#define T_LEN 1024
#define IN_D  20
#define HIDN  50
#define OUT_D 8
#define NB    4
#define NCTA  128
#define NTH   256

// shared memory layout (float offsets)
#define WA_STR 76          // cell1 row: 20 fused-x cols + 50 Whh1 cols + 6 pad
#define WA_OFF 0           // 200 x 76
#define WB_OFF 15200       // 200 x 100  [Wih2 | Whh2]
#define WC_OFF 35200       // 200 x 100  [Wih3 | Whh3]
#define BA_OFF 55200       // 200 fused bias cell1
#define BB_OFF 55400
#define BC_OFF 55600
#define W2_OFF 55800       // 8 x 50
#define B2_OFF 56200       // 8
#define IN1_OFF 56208      // 76 quads: [x_t(20) | h1(50) | pad(6)] x 4 batches
#define ST_OFF  56512      // 150 quads: h1(0..49) h2(50..99) h3(100..149)
#define ACT_OFF 57112      // 200 quads: activated gates
#define SMEM_FLT 57912     // 231,648 bytes

typedef unsigned long long ull;

static __device__ __forceinline__ ull pk2(float a) {
    ull r; asm("mov.b64 %0, {%1,%1};" : "=l"(r) : "f"(a)); return r;
}
static __device__ __forceinline__ void upk(ull v, float &a, float &b) {
    asm("mov.b64 {%0,%1}, %2;" : "=f"(a), "=f"(b) : "l"(v));
}
static __device__ __forceinline__ ull fma2(ull a, ull b, ull c) {
    ull d; asm("fma.rn.f32x2 %0, %1, %2, %3;" : "=l"(d) : "l"(a), "l"(b), "l"(c)); return d;
}
static __device__ __forceinline__ ull add2(ull a, ull b) {
    ull d; asm("add.rn.f32x2 %0, %1, %2;" : "=l"(d) : "l"(a), "l"(b)); return d;
}
static __device__ __forceinline__ float sigm(float x) {
    return __fdividef(1.f, 1.f + __expf(-x));
}
static __device__ __forceinline__ float tanh_(float x) {
    x = fminf(fmaxf(x, -15.f), 15.f);
    float e = __expf(-2.f * x);
    return __fdividef(1.f - e, 1.f + e);
}

// One gate row r for 4 batch elements; 4 independent FMA chains (2 packed x even/odd col).
template<int NQ>
static __device__ __forceinline__ void cell_mv(const float* __restrict__ wrow, float bias,
                                               const float* __restrict__ in,
                                               float* __restrict__ actq, int r)
{
    const float4* w4p = reinterpret_cast<const float4*>(wrow);
    const ulonglong2* q = reinterpret_cast<const ulonglong2*>(in);
    ull a01e = pk2(bias), a23e = a01e;
    ull a01o = 0ull,      a23o = 0ull;   // packed (0,0)
#pragma unroll
    for (int kk = 0; kk < NQ; kk++) {
        float4 w = w4p[kk];
        ulonglong2 q0 = q[4*kk+0], q1 = q[4*kk+1], q2 = q[4*kk+2], q3 = q[4*kk+3];
        ull w0 = pk2(w.x), w1 = pk2(w.y), w2 = pk2(w.z), w3 = pk2(w.w);
        a01e = fma2(w0, q0.x, a01e); a23e = fma2(w0, q0.y, a23e);
        a01o = fma2(w1, q1.x, a01o); a23o = fma2(w1, q1.y, a23o);
        a01e = fma2(w2, q2.x, a01e); a23e = fma2(w2, q2.y, a23e);
        a01o = fma2(w3, q3.x, a01o); a23o = fma2(w3, q3.y, a23o);
    }
    ull a01 = add2(a01e, a01o), a23 = add2(a23e, a23o);
    float g0, g1, g2, g3;
    upk(a01, g0, g1); upk(a23, g2, g3);
    if (r < 100 || r >= 150) {            // i, f, o gates -> sigmoid
        g0 = sigm(g0); g1 = sigm(g1); g2 = sigm(g2); g3 = sigm(g3);
    } else {                               // g gate -> tanh
        g0 = tanh_(g0); g1 = tanh_(g1); g2 = tanh_(g2); g3 = tanh_(g3);
    }
    reinterpret_cast<float4*>(actq)[r] = make_float4(g0, g1, g2, g3);
}

extern __shared__ float sm[];

__global__ void __launch_bounds__(NTH, 1)
lstm_persist_kernel(const float* __restrict__ x,
                    const float* __restrict__ W1,   const float* __restrict__ b1,
                    const float* __restrict__ Wih1, const float* __restrict__ Whh1,
                    const float* __restrict__ bih1, const float* __restrict__ bhh1,
                    const float* __restrict__ Wih2, const float* __restrict__ Whh2,
                    const float* __restrict__ bih2, const float* __restrict__ bhh2,
                    const float* __restrict__ Wih3, const float* __restrict__ Whh3,
                    const float* __restrict__ bih3, const float* __restrict__ bhh3,
                    const float* __restrict__ W2,   const float* __restrict__ b2,
                    float* __restrict__ out)
{
    const int tid = threadIdx.x;
    const int b0  = blockIdx.x * NB;

    // ---------------- init: build fused weights in SMEM ----------------
    for (int i = tid; i < HIDN * IN_D; i += NTH) sm[ST_OFF + i] = W1[i];
    __syncthreads();

    // WA x-part: Wc[r][k] = sum_j Wih1[r][j] * W1[j][k]
    for (int i = tid; i < 200 * IN_D; i += NTH) {
        int r = i / IN_D, k = i % IN_D;
        float acc = 0.f;
#pragma unroll 10
        for (int j = 0; j < HIDN; j++)
            acc += Wih1[r * HIDN + j] * sm[ST_OFF + j * IN_D + k];
        sm[WA_OFF + r * WA_STR + k] = acc;
    }
    for (int i = tid; i < 200 * 56; i += NTH) {
        int r = i / 56, c = i % 56;
        sm[WA_OFF + r * WA_STR + IN_D + c] = (c < HIDN) ? Whh1[r * HIDN + c] : 0.f;
    }
    for (int r = tid; r < 200; r += NTH) {
        float acc = bih1[r] + bhh1[r];
#pragma unroll 10
        for (int j = 0; j < HIDN; j++) acc += Wih1[r * HIDN + j] * b1[j];
        sm[BA_OFF + r] = acc;
        sm[BB_OFF + r] = bih2[r] + bhh2[r];
        sm[BC_OFF + r] = bih3[r] + bhh3[r];
    }
    for (int i = tid; i < 200 * 100; i += NTH) {
        int r = i / 100, c = i % 100;
        sm[WB_OFF + i] = (c < HIDN) ? Wih2[r * HIDN + c] : Whh2[r * HIDN + c - HIDN];
        sm[WC_OFF + i] = (c < HIDN) ? Wih3[r * HIDN + c] : Whh3[r * HIDN + c - HIDN];
    }
    for (int i = tid; i < OUT_D * HIDN; i += NTH) sm[W2_OFF + i] = W2[i];
    if (tid < OUT_D) sm[B2_OFF + tid] = b2[tid];
    __syncthreads();  // W1 staging reads complete before zeroing that region

    for (int i = 80 + tid; i < 304; i += NTH) sm[IN1_OFF + i] = 0.f;
    for (int i = tid; i < 600; i += NTH) sm[ST_OFF + i] = 0.f;
    for (int i = tid; i < 800; i += NTH) sm[ACT_OFF + i] = 0.f;
    if (tid < NB * IN_D) {
        int b = tid / IN_D, k = tid % IN_D;
        sm[IN1_OFF + k * NB + b] = x[((size_t)(b0 + b) * T_LEN) * IN_D + k];
    }
    __syncthreads();

    // ---------------- main recurrent loop ----------------
    const int r = tid;
    const bool isw7 = (tid >= 224);
    const int u = tid - 224;                  // warp-7 lane 0..31
    // warp-7 x-prefetch element assignments (80 elements over 32 lanes)
    const int e0 = u, e1 = u + 32, e2 = u + 64;
    const int ob = u >> 3, oo = u & 7;        // out-proj mapping (b, o)

    // per-hidden-unit cell states (threads tid<50); c3 stays 0 (ref bug),
    // cz carries "c2" = cell3's c_new from the previous step.
    float c1s[NB] = {0.f, 0.f, 0.f, 0.f};
    float czs[NB] = {0.f, 0.f, 0.f, 0.f};

    for (int t = 0; t < T_LEN; t++) {
        float xv0 = 0.f, xv1 = 0.f, xv2 = 0.f;
        const bool xl = (t + 1 < T_LEN);

        // ---- phase 1: gate1 || warp7 {x prefetch, out(t-1)} ----
        if (r < 200) {
            cell_mv<19>(sm + WA_OFF + r * WA_STR, sm[BA_OFF + r],
                        sm + IN1_OFF, sm + ACT_OFF, r);
        } else if (isw7) {
            if (xl) {  // issue x(t+1) loads early; store next phase
                { int b = e0 / IN_D, k = e0 % IN_D;
                  xv0 = x[((size_t)(b0 + b) * T_LEN + (t + 1)) * IN_D + k]; }
                { int b = e1 / IN_D, k = e1 % IN_D;
                  xv1 = x[((size_t)(b0 + b) * T_LEN + (t + 1)) * IN_D + k]; }
                if (e2 < NB * IN_D) {
                  int b = e2 / IN_D, k = e2 % IN_D;
                  xv2 = x[((size_t)(b0 + b) * T_LEN + (t + 1)) * IN_D + k]; }
            }
            if (t > 0) {  // out-projection for step t-1 (h3 stable until upd3)
                float acc = sm[B2_OFF + oo];
#pragma unroll
                for (int j = 0; j < HIDN; j++)
                    acc += sm[W2_OFF + oo * HIDN + j] * sm[ST_OFF + (100 + j) * NB + ob];
                out[((size_t)(b0 + ob) * T_LEN + (t - 1)) * OUT_D + oo] = acc;
            }
        }
        __syncthreads();

        // ---- phase 2: upd1 || warp7 stores x(t+1) ----
        if (r < HIDN) {
            float4 iq = reinterpret_cast<float4*>(sm + ACT_OFF)[r];
            float4 fq = reinterpret_cast<float4*>(sm + ACT_OFF)[50 + r];
            float4 gq = reinterpret_cast<float4*>(sm + ACT_OFF)[100 + r];
            float4 oq = reinterpret_cast<float4*>(sm + ACT_OFF)[150 + r];
            float h[NB];
            c1s[0] = fq.x * c1s[0] + iq.x * gq.x;  h[0] = oq.x * tanh_(c1s[0]);
            c1s[1] = fq.y * c1s[1] + iq.y * gq.y;  h[1] = oq.y * tanh_(c1s[1]);
            c1s[2] = fq.z * c1s[2] + iq.z * gq.z;  h[2] = oq.z * tanh_(c1s[2]);
            c1s[3] = fq.w * c1s[3] + iq.w * gq.w;  h[3] = oq.w * tanh_(c1s[3]);
            float4 hv = make_float4(h[0], h[1], h[2], h[3]);
            reinterpret_cast<float4*>(sm + ST_OFF)[r] = hv;            // h1 for cell2
            reinterpret_cast<float4*>(sm + IN1_OFF)[IN_D + r] = hv;    // h1 for next cell1
        } else if (isw7 && xl) {
            { int b = e0 / IN_D, k = e0 % IN_D; sm[IN1_OFF + k * NB + b] = xv0; }
            { int b = e1 / IN_D, k = e1 % IN_D; sm[IN1_OFF + k * NB + b] = xv1; }
            if (e2 < NB * IN_D) {
              int b = e2 / IN_D, k = e2 % IN_D; sm[IN1_OFF + k * NB + b] = xv2; }
        }
        __syncthreads();

        // ---- phase 3: gate2 from [h1 | h2] ----
        if (r < 200)
            cell_mv<25>(sm + WB_OFF + r * 100, sm[BB_OFF + r],
                        sm + ST_OFF, sm + ACT_OFF, r);
        __syncthreads();

        // ---- phase 4: upd2 (state = cz, cell3's c_new from prev step) ----
        if (r < HIDN) {
            float4 iq = reinterpret_cast<float4*>(sm + ACT_OFF)[r];
            float4 fq = reinterpret_cast<float4*>(sm + ACT_OFF)[50 + r];
            float4 gq = reinterpret_cast<float4*>(sm + ACT_OFF)[100 + r];
            float4 oq = reinterpret_cast<float4*>(sm + ACT_OFF)[150 + r];
            float c2t, h[NB];
            c2t = fq.x * czs[0] + iq.x * gq.x;  h[0] = oq.x * tanh_(c2t);
            c2t = fq.y * czs[1] + iq.y * gq.y;  h[1] = oq.y * tanh_(c2t);
            c2t = fq.z * czs[2] + iq.z * gq.z;  h[2] = oq.z * tanh_(c2t);
            c2t = fq.w * czs[3] + iq.w * gq.w;  h[3] = oq.w * tanh_(c2t);
            reinterpret_cast<float4*>(sm + ST_OFF)[50 + r] =
                make_float4(h[0], h[1], h[2], h[3]);                   // h2
        }
        __syncthreads();

        // ---- phase 5: gate3 from [h2 | h3]; c3 input always 0 ----
        if (r < 200)
            cell_mv<25>(sm + WC_OFF + r * 100, sm[BC_OFF + r],
                        sm + ST_OFF + 50 * NB, sm + ACT_OFF, r);
        __syncthreads();

        // ---- phase 6: upd3 (c_new = i*g; cz <- c_new) ----
        if (r < HIDN) {
            float4 iq = reinterpret_cast<float4*>(sm + ACT_OFF)[r];
            float4 gq = reinterpret_cast<float4*>(sm + ACT_OFF)[100 + r];
            float4 oq = reinterpret_cast<float4*>(sm + ACT_OFF)[150 + r];
            float h[NB];
            czs[0] = iq.x * gq.x;  h[0] = oq.x * tanh_(czs[0]);
            czs[1] = iq.y * gq.y;  h[1] = oq.y * tanh_(czs[1]);
            czs[2] = iq.z * gq.z;  h[2] = oq.z * tanh_(czs[2]);
            czs[3] = iq.w * gq.w;  h[3] = oq.w * tanh_(czs[3]);
            reinterpret_cast<float4*>(sm + ST_OFF)[100 + r] =
                make_float4(h[0], h[1], h[2], h[3]);                   // h3
        }
        __syncthreads();
    }

    // tail: out-projection for the final step
    if (isw7) {
        float acc = sm[B2_OFF + oo];
#pragma unroll
        for (int j = 0; j < HIDN; j++)
            acc += sm[W2_OFF + oo * HIDN + j] * sm[ST_OFF + (100 + j) * NB + ob];
        out[((size_t)(b0 + ob) * T_LEN + (T_LEN - 1)) * OUT_D + oo] = acc;
    }
}

extern "C" void kernel_launch(void* const* d_in, const int* in_sizes, int n_in,
                              void* d_out, int out_size)
{
    const float* x    = (const float*)d_in[0];
    const float* W1   = (const float*)d_in[1];
    const float* b1   = (const float*)d_in[2];
    const float* Wih1 = (const float*)d_in[3];
    const float* Whh1 = (const float*)d_in[4];
    const float* bih1 = (const float*)d_in[5];
    const float* bhh1 = (const float*)d_in[6];
    const float* Wih2 = (const float*)d_in[7];
    const float* Whh2 = (const float*)d_in[8];
    const float* bih2 = (const float*)d_in[9];
    const float* bhh2 = (const float*)d_in[10];
    const float* Wih3 = (const float*)d_in[11];
    const float* Whh3 = (const float*)d_in[12];
    const float* bih3 = (const float*)d_in[13];
    const float* bhh3 = (const float*)d_in[14];
    const float* W2   = (const float*)d_in[15];
    const float* b2   = (const float*)d_in[16];
    float* out = (float*)d_out;

    const int smem_bytes = SMEM_FLT * sizeof(float);  // 231,648
    cudaFuncSetAttribute(lstm_persist_kernel,
                         cudaFuncAttributeMaxDynamicSharedMemorySize, smem_bytes);

    lstm_persist_kernel<<<NCTA, NTH, smem_bytes>>>(
        x, W1, b1, Wih1, Whh1, bih1, bhh1,
        Wih2, Whh2, bih2, bhh2, Wih3, Whh3, bih3, bhh3,
        W2, b2, out);
}

// round 3
// speedup vs baseline: 1.1520x; 1.1520x over previous
#include <cuda_runtime.h>

// Net_2095944040841: 3-layer LSTM (reference's buggy c-state wiring) on GB300.
// R3: pair-packed f32x2 (no pk2 MOVs), 2 gate rows/thread (100 gate threads),
// helper warp for x-prefetch + out-projection overlap. 160 threads/CTA.

#define T_LEN 1024
#define IN_D  20
#define HIDN  50
#define OUT_D 8
#define NB    4
#define NCTA  128
#define NTH   160

// shared memory layout (float offsets)
#define WA_STR 76          // cell1 row: 20 fused-x cols + 50 Whh1 cols + 6 pad
#define WA_OFF 0           // 200 x 76
#define WB_OFF 15200       // 200 x 100  [Wih2 | Whh2]
#define WC_OFF 35200       // 200 x 100  [Wih3 | Whh3]
#define BA_OFF 55200       // 200 fused bias cell1
#define BB_OFF 55400
#define BC_OFF 55600
#define W2_OFF 55800       // 8 x 50
#define B2_OFF 56200       // 8
// pair-interleaved inputs: float[pair][batch][2]  (8 floats = 32B per pair)
#define IN1_OFF 56208      // 38 pairs: p0-9 = x(20 cols), p10-34 = h1, p35-37 = pad
#define ST_OFF  56512      // 75 pairs: h1 p0-24 (+0), h2 p25-49 (+200), h3 p50-74 (+400)
#define ACT_OFF 57112      // 200 quads [row][batch] of activated gates
#define SMEM_FLT 57912     // 231,648 bytes

typedef unsigned long long ull;

static __device__ __forceinline__ void upk(ull v, float &a, float &b) {
    asm("mov.b64 {%0,%1}, %2;" : "=f"(a), "=f"(b) : "l"(v));
}
static __device__ __forceinline__ ull fma2(ull a, ull b, ull c) {
    ull d; asm("fma.rn.f32x2 %0, %1, %2, %3;" : "=l"(d) : "l"(a), "l"(b), "l"(c)); return d;
}
static __device__ __forceinline__ float sigm(float x) {
    return __fdividef(1.f, 1.f + __expf(-x));
}
static __device__ __forceinline__ float tanh_(float x) {
    x = fminf(fmaxf(x, -15.f), 15.f);
    float e = __expf(-2.f * x);
    return __fdividef(1.f - e, 1.f + e);
}

// Two gate rows (r0 = g, r1 = g+100) for 4 batches. Weights are natural 64-bit
// (even,odd)-column pairs; inputs are pair-interleaved per batch. 8 acc chains.
template<int NQ>
static __device__ __forceinline__ void cell_mv2(
    const float* __restrict__ w0row, const float* __restrict__ w1row,
    float bias0, float bias1,
    const float* __restrict__ in, float* __restrict__ actq,
    int r0, int r1)
{
    const ulonglong2* w0q = reinterpret_cast<const ulonglong2*>(w0row);
    const ulonglong2* w1q = reinterpret_cast<const ulonglong2*>(w1row);
    const ulonglong2* q   = reinterpret_cast<const ulonglong2*>(in);
    ull a00 = 0ull, a01 = 0ull, a02 = 0ull, a03 = 0ull;   // row0, batches 0..3
    ull a10 = 0ull, a11 = 0ull, a12 = 0ull, a13 = 0ull;   // row1, batches 0..3
#pragma unroll
    for (int kk = 0; kk < NQ; kk++) {
        ulonglong2 w0 = w0q[kk], w1 = w1q[kk];            // 2 col-pairs per row
        ulonglong2 q0 = q[4*kk+0], q1 = q[4*kk+1];        // pair0: b01, b23
        ulonglong2 q2 = q[4*kk+2], q3 = q[4*kk+3];        // pair1: b01, b23
        a00 = fma2(w0.x, q0.x, a00); a01 = fma2(w0.x, q0.y, a01);
        a02 = fma2(w0.x, q1.x, a02); a03 = fma2(w0.x, q1.y, a03);
        a10 = fma2(w1.x, q0.x, a10); a11 = fma2(w1.x, q0.y, a11);
        a12 = fma2(w1.x, q1.x, a12); a13 = fma2(w1.x, q1.y, a13);
        a00 = fma2(w0.y, q2.x, a00); a01 = fma2(w0.y, q2.y, a01);
        a02 = fma2(w0.y, q3.x, a02); a03 = fma2(w0.y, q3.y, a03);
        a10 = fma2(w1.y, q2.x, a10); a11 = fma2(w1.y, q2.y, a11);
        a12 = fma2(w1.y, q3.x, a12); a13 = fma2(w1.y, q3.y, a13);
    }
    float g0[4], g1[4];
    { float lo, hi;
      upk(a00, lo, hi); g0[0] = lo + hi + bias0;
      upk(a01, lo, hi); g0[1] = lo + hi + bias0;
      upk(a02, lo, hi); g0[2] = lo + hi + bias0;
      upk(a03, lo, hi); g0[3] = lo + hi + bias0;
      upk(a10, lo, hi); g1[0] = lo + hi + bias1;
      upk(a11, lo, hi); g1[1] = lo + hi + bias1;
      upk(a12, lo, hi); g1[2] = lo + hi + bias1;
      upk(a13, lo, hi); g1[3] = lo + hi + bias1; }
    // row0 (i or f gate) -> sigmoid always
    g0[0] = sigm(g0[0]); g0[1] = sigm(g0[1]); g0[2] = sigm(g0[2]); g0[3] = sigm(g0[3]);
    // row1: g-gate (r1<150) -> tanh, else o-gate -> sigmoid (warp-uniform branch)
    if (r1 < 150) {
        g1[0] = tanh_(g1[0]); g1[1] = tanh_(g1[1]); g1[2] = tanh_(g1[2]); g1[3] = tanh_(g1[3]);
    } else {
        g1[0] = sigm(g1[0]); g1[1] = sigm(g1[1]); g1[2] = sigm(g1[2]); g1[3] = sigm(g1[3]);
    }
    reinterpret_cast<float4*>(actq)[r0] = make_float4(g0[0], g0[1], g0[2], g0[3]);
    reinterpret_cast<float4*>(actq)[r1] = make_float4(g1[0], g1[1], g1[2], g1[3]);
}

extern __shared__ float sm[];

__global__ void __launch_bounds__(NTH, 1)
lstm_persist_kernel(const float* __restrict__ x,
                    const float* __restrict__ W1,   const float* __restrict__ b1,
                    const float* __restrict__ Wih1, const float* __restrict__ Whh1,
                    const float* __restrict__ bih1, const float* __restrict__ bhh1,
                    const float* __restrict__ Wih2, const float* __restrict__ Whh2,
                    const float* __restrict__ bih2, const float* __restrict__ bhh2,
                    const float* __restrict__ Wih3, const float* __restrict__ Whh3,
                    const float* __restrict__ bih3, const float* __restrict__ bhh3,
                    const float* __restrict__ W2,   const float* __restrict__ b2,
                    float* __restrict__ out)
{
    const int tid = threadIdx.x;
    const int b0  = blockIdx.x * NB;

    // ---------------- init: build fused weights in SMEM ----------------
    // stage W1 (1000 floats) in ST/ACT scratch region
    for (int i = tid; i < HIDN * IN_D; i += NTH) sm[ST_OFF + i] = W1[i];
    __syncthreads();

    // WA x-part: Wc[r][k] = sum_j Wih1[r][j] * W1[j][k]
    for (int i = tid; i < 200 * IN_D; i += NTH) {
        int r = i / IN_D, k = i % IN_D;
        float acc = 0.f;
#pragma unroll 10
        for (int j = 0; j < HIDN; j++)
            acc += Wih1[r * HIDN + j] * sm[ST_OFF + j * IN_D + k];
        sm[WA_OFF + r * WA_STR + k] = acc;
    }
    for (int i = tid; i < 200 * 56; i += NTH) {
        int r = i / 56, c = i % 56;
        sm[WA_OFF + r * WA_STR + IN_D + c] = (c < HIDN) ? Whh1[r * HIDN + c] : 0.f;
    }
    for (int r = tid; r < 200; r += NTH) {
        float acc = bih1[r] + bhh1[r];
#pragma unroll 10
        for (int j = 0; j < HIDN; j++) acc += Wih1[r * HIDN + j] * b1[j];
        sm[BA_OFF + r] = acc;
        sm[BB_OFF + r] = bih2[r] + bhh2[r];
        sm[BC_OFF + r] = bih3[r] + bhh3[r];
    }
    for (int i = tid; i < 200 * 100; i += NTH) {
        int r = i / 100, c = i % 100;
        sm[WB_OFF + i] = (c < HIDN) ? Wih2[r * HIDN + c] : Whh2[r * HIDN + c - HIDN];
        sm[WC_OFF + i] = (c < HIDN) ? Wih3[r * HIDN + c] : Whh3[r * HIDN + c - HIDN];
    }
    for (int i = tid; i < OUT_D * HIDN; i += NTH) sm[W2_OFF + i] = W2[i];
    if (tid < OUT_D) sm[B2_OFF + tid] = b2[tid];
    __syncthreads();   // W1 staging reads complete

    // zero dynamic regions
    for (int i = tid; i < 304; i += NTH) sm[IN1_OFF + i] = 0.f;
    for (int i = tid; i < 600; i += NTH) sm[ST_OFF + i]  = 0.f;
    for (int i = tid; i < 800; i += NTH) sm[ACT_OFF + i] = 0.f;
    __syncthreads();
    // x(0) into IN1 pair layout: elem (b,k) -> (k>>1)*8 + 2b + (k&1)
    if (tid < NB * IN_D) {
        int b = tid / IN_D, k = tid % IN_D;
        sm[IN1_OFF + (k >> 1) * 8 + 2 * b + (k & 1)] =
            x[((size_t)(b0 + b) * T_LEN) * IN_D + k];
    }
    __syncthreads();

    // ---------------- main recurrent loop ----------------
    const int lane = tid & 31, wrp = tid >> 5;
    const bool isgate = (wrp < 4) && (lane < 25);
    const int g = wrp * 25 + lane;              // gate group 0..99 -> rows g, g+100
    const bool ishelp = (wrp == 4);
    const int u7 = tid - 128;                   // helper lane
    const int e0 = u7, e1 = u7 + 32, e2 = u7 + 64;
    const int ob = u7 >> 3, oo = u7 & 7;

    const float* wa0 = sm + WA_OFF + g * WA_STR;
    const float* wa1 = sm + WA_OFF + (g + 100) * WA_STR;
    const float* wb0 = sm + WB_OFF + g * 100;
    const float* wb1 = sm + WB_OFF + (g + 100) * 100;
    const float* wc0 = sm + WC_OFF + g * 100;
    const float* wc1 = sm + WC_OFF + (g + 100) * 100;
    const float ba0 = isgate ? sm[BA_OFF + g] : 0.f;
    const float ba1 = isgate ? sm[BA_OFF + g + 100] : 0.f;
    const float bb0 = isgate ? sm[BB_OFF + g] : 0.f;
    const float bb1 = isgate ? sm[BB_OFF + g + 100] : 0.f;
    const float bc0 = isgate ? sm[BC_OFF + g] : 0.f;
    const float bc1 = isgate ? sm[BC_OFF + g + 100] : 0.f;

    // cell states for unit u = tid (threads 0..49); c3 stays 0 (ref bug),
    // cz carries cell3's c_new from the previous step (acts as "c2").
    float c1s[NB] = {0.f, 0.f, 0.f, 0.f};
    float czs[NB] = {0.f, 0.f, 0.f, 0.f};
    const int up = tid >> 1, us = tid & 1;      // update thread's pair/slot

    for (int t = 0; t < T_LEN; t++) {
        float xv0 = 0.f, xv1 = 0.f, xv2 = 0.f;
        const bool xl = (t + 1 < T_LEN);

        // ---- phase 1: gate1 || helper {x(t+1) prefetch, out(t-1)} ----
        if (isgate) {
            cell_mv2<19>(wa0, wa1, ba0, ba1, sm + IN1_OFF, sm + ACT_OFF, g, g + 100);
        } else if (ishelp) {
            if (xl) {
                { int b = e0 / IN_D, k = e0 % IN_D;
                  xv0 = x[((size_t)(b0 + b) * T_LEN + (t + 1)) * IN_D + k]; }
                { int b = e1 / IN_D, k = e1 % IN_D;
                  xv1 = x[((size_t)(b0 + b) * T_LEN + (t + 1)) * IN_D + k]; }
                if (e2 < NB * IN_D) {
                  int b = e2 / IN_D, k = e2 % IN_D;
                  xv2 = x[((size_t)(b0 + b) * T_LEN + (t + 1)) * IN_D + k]; }
            }
            if (t > 0) {   // out-projection for step t-1 (h3 pairs at ST+400)
                float acc = sm[B2_OFF + oo];
#pragma unroll
                for (int j = 0; j < HIDN; j++)
                    acc += sm[W2_OFF + oo * HIDN + j] *
                           sm[ST_OFF + 400 + (j >> 1) * 8 + 2 * ob + (j & 1)];
                out[((size_t)(b0 + ob) * T_LEN + (t - 1)) * OUT_D + oo] = acc;
            }
        }
        __syncthreads();

        // ---- phase 2: upd1 || helper stores x(t+1) ----
        if (tid < HIDN) {
            float4 iq = reinterpret_cast<float4*>(sm + ACT_OFF)[tid];
            float4 fq = reinterpret_cast<float4*>(sm + ACT_OFF)[50 + tid];
            float4 gq = reinterpret_cast<float4*>(sm + ACT_OFF)[100 + tid];
            float4 oq = reinterpret_cast<float4*>(sm + ACT_OFF)[150 + tid];
            float h[NB];
            c1s[0] = fq.x * c1s[0] + iq.x * gq.x;  h[0] = oq.x * tanh_(c1s[0]);
            c1s[1] = fq.y * c1s[1] + iq.y * gq.y;  h[1] = oq.y * tanh_(c1s[1]);
            c1s[2] = fq.z * c1s[2] + iq.z * gq.z;  h[2] = oq.z * tanh_(c1s[2]);
            c1s[3] = fq.w * c1s[3] + iq.w * gq.w;  h[3] = oq.w * tanh_(c1s[3]);
            // h1 pairs for cell2 input and for next step's cell1 input
#pragma unroll
            for (int b = 0; b < NB; b++) {
                sm[ST_OFF  + up * 8 + 2 * b + us]        = h[b];
                sm[IN1_OFF + (10 + up) * 8 + 2 * b + us] = h[b];
            }
        } else if (ishelp && xl) {
            { int b = e0 / IN_D, k = e0 % IN_D;
              sm[IN1_OFF + (k >> 1) * 8 + 2 * b + (k & 1)] = xv0; }
            { int b = e1 / IN_D, k = e1 % IN_D;
              sm[IN1_OFF + (k >> 1) * 8 + 2 * b + (k & 1)] = xv1; }
            if (e2 < NB * IN_D) {
              int b = e2 / IN_D, k = e2 % IN_D;
              sm[IN1_OFF + (k >> 1) * 8 + 2 * b + (k & 1)] = xv2; }
        }
        __syncthreads();

        // ---- phase 3: gate2 from [h1 | h2] pairs ----
        if (isgate)
            cell_mv2<25>(wb0, wb1, bb0, bb1, sm + ST_OFF, sm + ACT_OFF, g, g + 100);
        __syncthreads();

        // ---- phase 4: upd2 (state = cz from prev step's cell3) ----
        if (tid < HIDN) {
            float4 iq = reinterpret_cast<float4*>(sm + ACT_OFF)[tid];
            float4 fq = reinterpret_cast<float4*>(sm + ACT_OFF)[50 + tid];
            float4 gq = reinterpret_cast<float4*>(sm + ACT_OFF)[100 + tid];
            float4 oq = reinterpret_cast<float4*>(sm + ACT_OFF)[150 + tid];
            float c2t, h[NB];
            c2t = fq.x * czs[0] + iq.x * gq.x;  h[0] = oq.x * tanh_(c2t);
            c2t = fq.y * czs[1] + iq.y * gq.y;  h[1] = oq.y * tanh_(c2t);
            c2t = fq.z * czs[2] + iq.z * gq.z;  h[2] = oq.z * tanh_(c2t);
            c2t = fq.w * czs[3] + iq.w * gq.w;  h[3] = oq.w * tanh_(c2t);
#pragma unroll
            for (int b = 0; b < NB; b++)
                sm[ST_OFF + 200 + up * 8 + 2 * b + us] = h[b];   // h2 pairs
        }
        __syncthreads();

        // ---- phase 5: gate3 from [h2 | h3] pairs ----
        if (isgate)
            cell_mv2<25>(wc0, wc1, bc0, bc1, sm + ST_OFF + 200, sm + ACT_OFF, g, g + 100);
        __syncthreads();

        // ---- phase 6: upd3 (c_new = i*g; cz <- c_new) ----
        if (tid < HIDN) {
            float4 iq = reinterpret_cast<float4*>(sm + ACT_OFF)[tid];
            float4 gq = reinterpret_cast<float4*>(sm + ACT_OFF)[100 + tid];
            float4 oq = reinterpret_cast<float4*>(sm + ACT_OFF)[150 + tid];
            float h[NB];
            czs[0] = iq.x * gq.x;  h[0] = oq.x * tanh_(czs[0]);
            czs[1] = iq.y * gq.y;  h[1] = oq.y * tanh_(czs[1]);
            czs[2] = iq.z * gq.z;  h[2] = oq.z * tanh_(czs[2]);
            czs[3] = iq.w * gq.w;  h[3] = oq.w * tanh_(czs[3]);
#pragma unroll
            for (int b = 0; b < NB; b++)
                sm[ST_OFF + 400 + up * 8 + 2 * b + us] = h[b];   // h3 pairs
        }
        __syncthreads();
    }

    // tail: out-projection for the final step
    if (ishelp) {
        float acc = sm[B2_OFF + oo];
#pragma unroll
        for (int j = 0; j < HIDN; j++)
            acc += sm[W2_OFF + oo * HIDN + j] *
                   sm[ST_OFF + 400 + (j >> 1) * 8 + 2 * ob + (j & 1)];
        out[((size_t)(b0 + ob) * T_LEN + (T_LEN - 1)) * OUT_D + oo] = acc;
    }
}

extern "C" void kernel_launch(void* const* d_in, const int* in_sizes, int n_in,
                              void* d_out, int out_size)
{
    const float* x    = (const float*)d_in[0];
    const float* W1   = (const float*)d_in[1];
    const float* b1   = (const float*)d_in[2];
    const float* Wih1 = (const float*)d_in[3];
    const float* Whh1 = (const float*)d_in[4];
    const float* bih1 = (const float*)d_in[5];
    const float* bhh1 = (const float*)d_in[6];
    const float* Wih2 = (const float*)d_in[7];
    const float* Whh2 = (const float*)d_in[8];
    const float* bih2 = (const float*)d_in[9];
    const float* bhh2 = (const float*)d_in[10];
    const float* Wih3 = (const float*)d_in[11];
    const float* Whh3 = (const float*)d_in[12];
    const float* bih3 = (const float*)d_in[13];
    const float* bhh3 = (const float*)d_in[14];
    const float* W2   = (const float*)d_in[15];
    const float* b2   = (const float*)d_in[16];
    float* out = (float*)d_out;

    const int smem_bytes = SMEM_FLT * sizeof(float);  // 231,648
    cudaFuncSetAttribute(lstm_persist_kernel,
                         cudaFuncAttributeMaxDynamicSharedMemorySize, smem_bytes);

    lstm_persist_kernel<<<NCTA, NTH, smem_bytes>>>(
        x, W1, b1, Wih1, Whh1, bih1, bhh1,
        Wih2, Whh2, bih2, bhh2, Wih3, Whh3, bih3, bhh3,
        W2, b2, out);
}